// round 15
// baseline (speedup 1.0000x reference)
#include <cuda_runtime.h>
#include <math.h>

#define W  2048
#define H  2048
#define NIMG 16

#define STRIP_OUT 248            // output columns per warp strip (8/lane)
#define NSTRIPS   9              // ceil(2048/248)
#define ROWT      128            // output rows per warp job
#define NROWT     16             // 2048/128
#define WARPS_PER_BLOCK 4
#define NTHREADS (WARPS_PER_BLOCK * 32)
#define NJOBS (NIMG * NROWT * NSTRIPS)          // 2304
#define NBLOCKS (NJOBS / WARPS_PER_BLOCK)       // 576  -> single wave @ 4 blk/SM

#define NEGINF (-__int_as_float(0x7f800000))

__device__ __forceinline__ float fsqrt_fast(float x)
{
    float r;
    asm("sqrt.approx.f32 %0, %1;" : "=f"(r) : "f"(x));
    return r;
}

__device__ __forceinline__ float4 ld4(const float* __restrict__ im,
                                      int y, int c, bool ok)
{
    if (!((unsigned)y < (unsigned)H) || !ok) return make_float4(0.f, 0.f, 0.f, 0.f);
    return *reinterpret_cast<const float4*>(im + (size_t)y * W + c);
}

// Two-phase register rotation: PH is a literal 0/1. Ring arrays swap ROLES
// per phase instead of being copied, so no ring-shift MOVs exist at all.
// Invariants at entry of a body for input row y:
//   phase 0: hOld=ha=h(y-2)  hMid=hb=h(y-1);  writes hc -> ha
//   phase 1: hOld=hb         hMid=ha;         writes hc -> hb
//   sm:  phase 0: old=sa, mid=sb, write->sa ; phase 1 mirrored
//   e:   phase 0: read ea (=e(y-3)), write ec->eb ; phase 1 mirrored
//   m:   phase 0: m(k-2)=ma, m(k-1)=mb, write mc->ma ; phase 1 mirrored
//   nx:  phase 0: cur=n1*, refill n1* with row y+2 ; phase 1 uses n2*
#define BODY(IY, PH, DO_SM, DO_E, DO_ST) do {                                    \
    const int y_ = ybase + (IY);                                                 \
    float cur[8];                                                                \
    if ((PH) == 0) {                                                             \
        cur[0]=n1a.x; cur[1]=n1a.y; cur[2]=n1a.z; cur[3]=n1a.w;                  \
        cur[4]=n1b.x; cur[5]=n1b.y; cur[6]=n1b.z; cur[7]=n1b.w;                  \
        n1a = ld4(im, y_ + 2, c0,     okA);                                      \
        n1b = ld4(im, y_ + 2, c0 + 4, okB);                                      \
    } else {                                                                     \
        cur[0]=n2a.x; cur[1]=n2a.y; cur[2]=n2a.z; cur[3]=n2a.w;                  \
        cur[4]=n2b.x; cur[5]=n2b.y; cur[6]=n2b.z; cur[7]=n2b.w;                  \
        n2a = ld4(im, y_ + 2, c0,     okA);                                      \
        n2b = ld4(im, y_ + 2, c0 + 4, okB);                                      \
    }                                                                            \
    float hc[8];                                                                 \
    {                                                                            \
        float inm1 = __shfl_up_sync(0xffffffffu, cur[7], 1);                     \
        float inp8 = __shfl_down_sync(0xffffffffu, cur[0], 1);                   \
        hc[0] = inm1 + 2.f*cur[0] + cur[1];                                      \
        _Pragma("unroll") for (int j = 1; j < 7; j++)                            \
            hc[j] = cur[j-1] + 2.f*cur[j] + cur[j+1];                            \
        hc[7] = cur[6] + 2.f*cur[7] + inp8;                                      \
    }                                                                            \
    if (DO_SM) {                                                                 \
        const bool rowok = ((unsigned)(y_ - 1) < (unsigned)H);                   \
        const float mskA = rowok ? cmulA : 0.f;                                  \
        const float mskB = rowok ? cmulB : 0.f;                                  \
        float smc[8];                                                            \
        _Pragma("unroll") for (int j = 0; j < 4; j++)                            \
            smc[j] = (((PH)==0 ? ha[j] : hb[j]) +                                \
                      2.f*((PH)==0 ? hb[j] : ha[j]) + hc[j]) * mskA;             \
        _Pragma("unroll") for (int j = 4; j < 8; j++)                            \
            smc[j] = (((PH)==0 ? ha[j] : hb[j]) +                                \
                      2.f*((PH)==0 ? hb[j] : ha[j]) + hc[j]) * mskB;             \
        if (DO_E) {                                                              \
            float vs[8], vd[8];                                                  \
            _Pragma("unroll") for (int j = 0; j < 8; j++) {                      \
                float sOld = (PH)==0 ? sa[j] : sb[j];                            \
                float sMid = (PH)==0 ? sb[j] : sa[j];                            \
                vs[j] = sOld + 2.f*sMid + smc[j];                                \
                vd[j] = smc[j] - sOld;                                           \
            }                                                                    \
            float vsm1 = __shfl_up_sync(0xffffffffu, vs[7], 1);                  \
            float vsp8 = __shfl_down_sync(0xffffffffu, vs[0], 1);                \
            float vdm1 = __shfl_up_sync(0xffffffffu, vd[7], 1);                  \
            float vdp8 = __shfl_down_sync(0xffffffffu, vd[0], 1);                \
            float ec[8];                                                         \
            {                                                                    \
                float gx, gy;                                                    \
                gx = vs[1] - vsm1; gy = vdm1 + 2.f*vd[0] + vd[1];                \
                ec[0] = fsqrt_fast(gx*gx + gy*gy);                               \
                _Pragma("unroll") for (int j = 1; j < 7; j++) {                  \
                    gx = vs[j+1] - vs[j-1];                                      \
                    gy = vd[j-1] + 2.f*vd[j] + vd[j+1];                          \
                    ec[j] = fsqrt_fast(gx*gx + gy*gy);                           \
                }                                                                \
                gx = vsp8 - vs[6]; gy = vd[6] + 2.f*vd[7] + vdp8;                \
                ec[7] = fsqrt_fast(gx*gx + gy*gy);                               \
            }                                                                    \
            float el = __shfl_up_sync(0xffffffffu, ec[7], 1);                    \
            float er = __shfl_down_sync(0xffffffffu, ec[0], 1);                  \
            float mc[8];                                                         \
            mc[0] = fmaxf(fmaxf(el, ec[0]), ec[1]);                              \
            _Pragma("unroll") for (int j = 1; j < 7; j++)                        \
                mc[j] = fmaxf(fmaxf(ec[j-1], ec[j]), ec[j+1]);                   \
            mc[7] = fmaxf(fmaxf(ec[6], ec[7]), er);                              \
            if (DO_ST) {                                                         \
                const int yo_ = y_ - 3;                                          \
                float r[8];                                                      \
                if ((yo_ > 0) && (yo_ < H - 1)) {   /* warp-uniform branch */    \
                    _Pragma("unroll") for (int j = 0; j < 8; j++) {              \
                        float eCen = (PH)==0 ? ea[j] : eb[j];                    \
                        float nm = fmaxf(fmaxf(ma[j], mb[j]), mc[j])             \
                                   + colmsk[j];                                  \
                        r[j] = (eCen < nm) ? 0.f : eCen;                         \
                    }                                                            \
                } else {                                                         \
                    _Pragma("unroll") for (int j = 0; j < 8; j++)                \
                        r[j] = (PH)==0 ? ea[j] : eb[j];                          \
                }                                                                \
                if (storerA)                                                     \
                    *reinterpret_cast<float4*>(op + (size_t)yo_ * W + c0) =      \
                        make_float4(r[0], r[1], r[2], r[3]);                     \
                if (storerB)                                                     \
                    *reinterpret_cast<float4*>(op + (size_t)yo_ * W + c0 + 4) =  \
                        make_float4(r[4], r[5], r[6], r[7]);                     \
            }                                                                    \
            _Pragma("unroll") for (int j = 0; j < 8; j++) {                      \
                if ((PH) == 0) { eb[j] = ec[j]; ma[j] = mc[j]; }                 \
                else           { ea[j] = ec[j]; mb[j] = mc[j]; }                 \
            }                                                                    \
        }                                                                        \
        _Pragma("unroll") for (int j = 0; j < 8; j++) {                          \
            if ((PH) == 0) sa[j] = smc[j]; else sb[j] = smc[j];                  \
        }                                                                        \
    }                                                                            \
    _Pragma("unroll") for (int j = 0; j < 8; j++) {                              \
        if ((PH) == 0) ha[j] = hc[j]; else hb[j] = hc[j];                        \
    }                                                                            \
} while (0)

__global__ __launch_bounds__(NTHREADS, 4)
void edge_kernel(const float* __restrict__ img, float* __restrict__ out)
{
    const int lane = threadIdx.x & 31;
    const int warp = threadIdx.x >> 5;
    const int job  = blockIdx.x * WARPS_PER_BLOCK + warp;

    const int strip = job % NSTRIPS;
    const int t     = job / NSTRIPS;
    const int rowt  = t % NROWT;
    const int n     = t / NROWT;

    const int cb = strip * STRIP_OUT - 4;   // loaded column base (mult of 4)
    const int c0 = cb + lane * 8;           // this lane's first column
    const int y0 = rowt * ROWT;
    const int ybase = y0 - 3;

    const float* im = img + (size_t)n * H * W;
    float*       op = out + (size_t)n * H * W;

    // per-float4-group validity (groups are 4-aligned; W % 4 == 0)
    const bool okA = (c0     >= 0) && (c0     < W);
    const bool okB = (c0 + 4 >= 0) && (c0 + 4 < W);
    const float cmulA = okA ? 0.0625f : 0.f;
    const float cmulB = okB ? 0.0625f : 0.f;

    // stores: warp outputs cols cb+4 .. cb+251
    const bool storerA = (lane > 0)  && okA;
    const bool storerB = (lane < 31) && okB;

    // 0 interior, -inf at global col borders (kills suppression there)
    float colmsk[8];
    #pragma unroll
    for (int j = 0; j < 8; j++)
        colmsk[j] = ((c0 + j > 0) && (c0 + j < W - 1)) ? 0.f : NEGINF;

    float ha[8], hb[8], sa[8], sb[8], ea[8], eb[8], ma[8], mb[8];
    #pragma unroll
    for (int j = 0; j < 8; j++) {
        ha[j]=hb[j]=0.f; sa[j]=sb[j]=0.f; ea[j]=eb[j]=0.f; ma[j]=mb[j]=0.f;
    }

    // 2-deep row prefetch, phase-alternating consume/refill (no copies)
    float4 n1a = ld4(im, ybase,     c0,     okA);
    float4 n1b = ld4(im, ybase,     c0 + 4, okB);
    float4 n2a = ld4(im, ybase + 1, c0,     okA);
    float4 n2b = ld4(im, ybase + 1, c0 + 4, okB);

    // ---- warmup: 8 specialized iterations, phases 0,1,0,1,... ----
    BODY(0, 0, false, false, false);
    BODY(1, 1, false, false, false);
    BODY(2, 0, true,  false, false);
    BODY(3, 1, true,  false, false);
    BODY(4, 0, true,  true,  false);
    BODY(5, 1, true,  true,  false);
    BODY(6, 0, true,  true,  true);
    BODY(7, 1, true,  true,  true);

    // ---- steady: iy = 8 .. ROWT+5 (126 iters = 63 phase pairs) ----
    for (int base = 8; base < ROWT + 6; base += 2) {
        BODY(base + 0, 0, true, true, true);
        BODY(base + 1, 1, true, true, true);
    }
}

extern "C" void kernel_launch(void* const* d_in, const int* in_sizes, int n_in,
                              void* d_out, int out_size)
{
    const float* img = (const float*)d_in[0];
    float* out = (float*)d_out;
    edge_kernel<<<NBLOCKS, NTHREADS>>>(img, out);
}